// round 14
// baseline (speedup 1.0000x reference)
#include <cuda_runtime.h>
#include <cuda_fp16.h>

#define NN   100000
#define INF  128
#define OUTF 64
#define NE_MAX 3200000
#define SCAN_B 1024
#define NBLK  ((NN + SCAN_B - 1) / SCAN_B)   // 98
#define WPAD  72

// Scratch (allocation-free rule: __device__ globals)
__device__ __half g_xws_h[(size_t)NN * OUTF]; // fp16 (X@W)*rsqrt(deg_out)
__device__ int    g_deg_out[NN];
__device__ int    g_deg_in[NN];
__device__ int    g_row_off[NN];              // CSR row start (by dst)
__device__ int    g_rank[NE_MAX];             // per-edge rank within dst row
__device__ int    g_csr_src[NE_MAX];
__device__ int    g_blocksum[NBLK];

// ---------------------------------------------------------------------------
__global__ void zero_kernel() {
    int t = blockIdx.x * blockDim.x + threadIdx.x;
    int stride = gridDim.x * blockDim.x;
    for (int j = t; j < NN; j += stride) {
        g_deg_out[j] = 0;
        g_deg_in[j]  = 0;
    }
}

// ---------------------------------------------------------------------------
// Out-degree histogram (src side). Result unused -> REDG, no return trip.
// Feeds only the GEMM (main stream).
// ---------------------------------------------------------------------------
__global__ void degree_out_kernel(const int* __restrict__ src, int E) {
    int stride = gridDim.x * blockDim.x;
    for (int e = blockIdx.x * blockDim.x + threadIdx.x; e < E; e += stride) {
        int s = src[e];
        if ((unsigned)s < NN) atomicAdd(&g_deg_out[s], 1);
    }
}

// ---------------------------------------------------------------------------
// In-degree histogram + per-edge rank (dst side). Feeds the scan/fill chain
// (side stream). The atomic's return value (already paid for) is the rank.
// ---------------------------------------------------------------------------
__global__ void degree_in_rank_kernel(const int* __restrict__ dst, int E) {
    int stride = gridDim.x * blockDim.x;
    for (int e = blockIdx.x * blockDim.x + threadIdx.x; e < E; e += stride) {
        int d = dst[e];
        if ((unsigned)d < NN) g_rank[e] = atomicAdd(&g_deg_in[d], 1);
    }
}

// ---------------------------------------------------------------------------
// Exclusive scan of g_deg_in -> g_row_off  (2 passes)
// ---------------------------------------------------------------------------
__global__ __launch_bounds__(SCAN_B) void scan_local_kernel() {
    __shared__ int sm[SCAN_B];
    int tid = threadIdx.x;
    int gid = blockIdx.x * SCAN_B + tid;
    int val = (gid < NN) ? g_deg_in[gid] : 0;
    sm[tid] = val;
    __syncthreads();
    #pragma unroll
    for (int off = 1; off < SCAN_B; off <<= 1) {
        int t = (tid >= off) ? sm[tid - off] : 0;
        __syncthreads();
        sm[tid] += t;
        __syncthreads();
    }
    if (gid < NN) g_row_off[gid] = sm[tid] - val;   // exclusive (local)
    if (tid == SCAN_B - 1) g_blocksum[blockIdx.x] = sm[tid];
}

__global__ __launch_bounds__(SCAN_B) void scan_add_kernel() {
    __shared__ int s_off;
    int tid = threadIdx.x;
    if (tid < 32) {                       // warp 0: prefix of blocksums
        int acc = 0;
        for (int i = tid; i < blockIdx.x; i += 32)
            acc += g_blocksum[i];
        #pragma unroll
        for (int o = 16; o > 0; o >>= 1)
            acc += __shfl_down_sync(0xffffffffu, acc, o);
        if (tid == 0) s_off = acc;
    }
    __syncthreads();
    int gid = blockIdx.x * SCAN_B + tid;
    if (gid < NN)
        g_row_off[gid] += s_off;
}

// ---------------------------------------------------------------------------
// CSR fill, atomic-free: pos = row_off[dst] + rank
// ---------------------------------------------------------------------------
__global__ void csr_fill_kernel(const int* __restrict__ src,
                                const int* __restrict__ dst, int E) {
    int stride = gridDim.x * blockDim.x;
    for (int e = blockIdx.x * blockDim.x + threadIdx.x; e < E; e += stride) {
        int s = src[e], d = dst[e];
        if ((unsigned)s >= NN || (unsigned)d >= NN) continue;
        int pos = __ldg(&g_row_off[d]) + g_rank[e];
        g_csr_src[pos] = s;
    }
}

// ---------------------------------------------------------------------------
// Tensor-core GEMM: xws = fp16( (A @ W) * rsqrt(max(deg_out,1)) )
// mma.sync.m16n8k8 tf32. One warp = 16 rows x 64 cols. (trusted R9 version)
// ---------------------------------------------------------------------------
__global__ __launch_bounds__(256) void gemm_mma_kernel(
    const float* __restrict__ A, const float* __restrict__ W, int n) {
    __shared__ unsigned Ws[INF][WPAD];
    int tid = threadIdx.x;
    for (int i = tid; i < INF * OUTF; i += 256) {
        int k = i >> 6, c = i & 63;
        unsigned t;
        asm("cvt.rna.tf32.f32 %0, %1;" : "=r"(t) : "f"(W[i]));
        Ws[k][c] = t;
    }
    __syncthreads();

    int warp = tid >> 5;
    int lane = tid & 31;
    int g  = lane >> 2;
    int tg = lane & 3;
    int row0 = (blockIdx.x * 8 + warp) * 16;

    int r_lo = row0 + g;
    int r_hi = row0 + g + 8;
    int r_lo_c = r_lo < n ? r_lo : n - 1;
    int r_hi_c = r_hi < n ? r_hi : n - 1;
    const float* Alo = A + (size_t)r_lo_c * INF;
    const float* Ahi = A + (size_t)r_hi_c * INF;

    float acc[8][4];
    #pragma unroll
    for (int nt = 0; nt < 8; nt++)
        #pragma unroll
        for (int c = 0; c < 4; c++) acc[nt][c] = 0.f;

    #pragma unroll
    for (int kk = 0; kk < 16; kk++) {
        int k0 = kk * 8;
        float a0f = __ldg(&Alo[k0 + tg]);
        float a1f = __ldg(&Ahi[k0 + tg]);
        float a2f = __ldg(&Alo[k0 + tg + 4]);
        float a3f = __ldg(&Ahi[k0 + tg + 4]);
        unsigned a0, a1, a2, a3;
        asm("cvt.rna.tf32.f32 %0, %1;" : "=r"(a0) : "f"(a0f));
        asm("cvt.rna.tf32.f32 %0, %1;" : "=r"(a1) : "f"(a1f));
        asm("cvt.rna.tf32.f32 %0, %1;" : "=r"(a2) : "f"(a2f));
        asm("cvt.rna.tf32.f32 %0, %1;" : "=r"(a3) : "f"(a3f));
        #pragma unroll
        for (int nt = 0; nt < 8; nt++) {
            unsigned b0 = Ws[k0 + tg][nt * 8 + g];
            unsigned b1 = Ws[k0 + tg + 4][nt * 8 + g];
            asm("mma.sync.aligned.m16n8k8.row.col.f32.tf32.tf32.f32 "
                "{%0,%1,%2,%3}, {%4,%5,%6,%7}, {%8,%9}, {%0,%1,%2,%3};"
                : "+f"(acc[nt][0]), "+f"(acc[nt][1]),
                  "+f"(acc[nt][2]), "+f"(acc[nt][3])
                : "r"(a0), "r"(a1), "r"(a2), "r"(a3), "r"(b0), "r"(b1));
        }
    }

    float s_lo = 1.f, s_hi = 1.f;
    if (r_lo < n) {
        int dg = g_deg_out[r_lo];
        s_lo = rsqrtf((float)(dg > 0 ? dg : 1));
    }
    if (r_hi < n) {
        int dg = g_deg_out[r_hi];
        s_hi = rsqrtf((float)(dg > 0 ? dg : 1));
    }
    #pragma unroll
    for (int nt = 0; nt < 8; nt++) {
        int col = nt * 8 + 2 * tg;
        if (r_lo < n) {
            __half2 h = __floats2half2_rn(acc[nt][0] * s_lo, acc[nt][1] * s_lo);
            *(__half2*)&g_xws_h[(size_t)r_lo * OUTF + col] = h;
        }
        if (r_hi < n) {
            __half2 h = __floats2half2_rn(acc[nt][2] * s_hi, acc[nt][3] * s_hi);
            *(__half2*)&g_xws_h[(size_t)r_hi * OUTF + col] = h;
        }
    }
}

// ---------------------------------------------------------------------------
// Aggregate: one warp per dst node, MLP=8 (measured best).
// ---------------------------------------------------------------------------
__global__ __launch_bounds__(256) void aggregate_kernel(
    float* __restrict__ out, const float* __restrict__ b, int n) {
    int warp = (blockIdx.x * blockDim.x + threadIdx.x) >> 5;
    if (warp >= n) return;
    int lane = threadIdx.x & 31;

    int start = g_row_off[warp];
    int deg   = g_deg_in[warp];

    float accx = 0.f, accy = 0.f;
    const __half2* base = (const __half2*)g_xws_h;

    for (int e0 = 0; e0 < deg; e0 += 32) {
        int me  = e0 + lane;
        int s   = (me < deg) ? __ldg(&g_csr_src[start + me]) : 0;
        int cnt = deg - e0; if (cnt > 32) cnt = 32;
        int j = 0;
        #pragma unroll 1
        for (; j + 8 <= cnt; j += 8) {
            int si[8];
            #pragma unroll
            for (int q = 0; q < 8; q++)
                si[q] = __shfl_sync(0xffffffffu, s, j + q);
            __half2 v[8];
            #pragma unroll
            for (int q = 0; q < 8; q++)
                v[q] = __ldg(base + (size_t)si[q] * 32 + lane);
            #pragma unroll
            for (int q = 0; q < 8; q++) {
                float2 f = __half22float2(v[q]);
                accx += f.x;
                accy += f.y;
            }
        }
        for (; j < cnt; j++) {
            int sj = __shfl_sync(0xffffffffu, s, j);
            float2 f = __half22float2(__ldg(base + (size_t)sj * 32 + lane));
            accx += f.x;
            accy += f.y;
        }
    }

    float sc = rsqrtf((float)(deg > 0 ? deg : 1));
    float2 bb = __ldg((const float2*)b + lane);
    float2 r;
    r.x = fmaxf(fmaf(accx, sc, bb.x), 0.f);
    r.y = fmaxf(fmaf(accy, sc, bb.y), 0.f);
    ((float2*)out)[(size_t)warp * 32 + lane] = r;
}

// ---------------------------------------------------------------------------
// Fork/join moved up to after zero_kernel:
//   main: deg_out -> GEMM            (src-side histogram feeds GEMM only)
//   side: deg_in+rank -> scan -> fill (dst-side chain feeds aggregate only)
// ---------------------------------------------------------------------------
extern "C" void kernel_launch(void* const* d_in, const int* in_sizes, int n_in,
                              void* d_out, int out_size) {
    const float* in_feat = (const float*)d_in[0];
    const int*   src     = (const int*)d_in[1];
    const int*   dst     = (const int*)d_in[2];
    const float* W       = (const float*)d_in[3];
    const float* b       = (const float*)d_in[4];
    float*       out     = (float*)d_out;

    int n = in_sizes[0] / INF;
    int E = in_sizes[1];

    static cudaStream_t sA = nullptr;
    static cudaEvent_t  evZ = nullptr, evF = nullptr;
    if (!sA) {   // one-time infra setup (first call is outside graph capture)
        cudaStreamCreateWithFlags(&sA, cudaStreamNonBlocking);
        cudaEventCreateWithFlags(&evZ, cudaEventDisableTiming);
        cudaEventCreateWithFlags(&evF, cudaEventDisableTiming);
    }

    zero_kernel<<<512, 256>>>();
    cudaEventRecord(evZ, 0);

    // side stream: dst-side chain (deg_in+rank -> scan -> fill)
    cudaStreamWaitEvent(sA, evZ, 0);
    degree_in_rank_kernel<<<2048, 256, 0, sA>>>(dst, E);
    scan_local_kernel<<<NBLK, SCAN_B, 0, sA>>>();
    scan_add_kernel<<<NBLK, SCAN_B, 0, sA>>>();
    csr_fill_kernel<<<2048, 256, 0, sA>>>(src, dst, E);
    cudaEventRecord(evF, sA);

    // main stream: src-side histogram then GEMM
    degree_out_kernel<<<2048, 256>>>(src, E);
    gemm_mma_kernel<<<(n + 127) / 128, 256>>>(in_feat, W, n);

    cudaStreamWaitEvent(0, evF, 0);
    aggregate_kernel<<<(n * 32 + 255) / 256, 256>>>(out, b, n);
}